// round 7
// baseline (speedup 1.0000x reference)
#include <cuda_runtime.h>
#include <cuda_bf16.h>

// CenterNet GT heatmap rendering — single-kernel tiled gather with culling.
//
// hm:      [N, C, H, W] f32 (shape-only)      -> d_in[0]
// bboxes:  [N, NOBJ, 5] f32 (x1,y1,x2,y2,val) -> d_in[1]
// out:     [N, C, H, W] f32, C == 1
//
// One block per (batch, 32x8 tile). Phase 1: threads 0..127 compute the
// per-object gaussian params and append objects intersecting this tile into
// a smem list. Phase 2: each thread owns one pixel, max-reduces over the
// culled list (broadcast LDS.128 reads), and writes a coalesced store.
// No atomics, no init kernel, one graph node.

#define HN 16
#define HC 1
#define HH 128
#define HW 128
#define NOBJ 128
#define TILE_W 32
#define TILE_H 8
#define TILES_X (HW / TILE_W)          // 4
#define TILES_Y (HH / TILE_H)          // 16
#define NTILES  (TILES_X * TILES_Y)    // 64
#define MIN_OVERLAP 0.7f

__device__ __forceinline__ float gaussian_radius_f(float w, float h) {
    // mirrors the reference fp32 math op-for-op
    const float mo = MIN_OVERLAP;
    float b1 = h + w;
    float c1 = w * h * (1.0f - mo) / (1.0f + mo);
    float sq1 = sqrtf(b1 * b1 - 4.0f * 1.0f * c1);
    float r1 = (b1 + sq1) * 0.5f;

    float b2 = 2.0f * (h + w);
    float c2 = (1.0f - mo) * w * h;
    float sq2 = sqrtf(b2 * b2 - 4.0f * 4.0f * c2);
    float r2 = (b2 + sq2) * 0.5f;

    float a3 = 4.0f * mo;
    float b3 = -2.0f * mo * (h + w);
    float c3 = (mo - 1.0f) * w * h;
    float sq3 = sqrtf(b3 * b3 - 4.0f * a3 * c3);
    float r3 = (b3 + sq3) * 0.5f;

    return fminf(fminf(r1, r2), r3);
}

__global__ void __launch_bounds__(256)
cn_gather_kernel(const float* __restrict__ bboxes,
                 float* __restrict__ out) {
    __shared__ float4 s_par[NOBJ];     // {cx, cy, r, -1/(2*sigma^2)} as floats
    __shared__ int    s_list[NOBJ];
    __shared__ int    s_cnt;

    const int tid   = threadIdx.x;
    const int tile  = blockIdx.x;      // 0..63
    const int batch = blockIdx.y;      // 0..15

    const int tx = (tile % TILES_X) * TILE_W;   // tile origin x
    const int ty = (tile / TILES_X) * TILE_H;   // tile origin y

    if (tid == 0) s_cnt = 0;
    __syncthreads();

    // ---- Phase 1: per-object params + tile culling (threads 0..127) ----
    if (tid < NOBJ) {
        const float* p = bboxes + (batch * NOBJ + tid) * 5;
        float x1 = p[0] * (float)HW;
        float y1 = p[1] * (float)HH;
        float x2 = p[2] * (float)HW;
        float y2 = p[3] * (float)HH;
        float valf = p[4];
        float bw = x2 - x1;
        float bh = y2 - y1;

        bool valid = (valf == 1.0f) && (bw > 0.0f) && (bh > 0.0f);
        if (valid) {
            float r = gaussian_radius_f(bw, bh);
            if (!(r == r)) r = 0.0f;        // jnp.nan_to_num
            r = fmaxf(r, 0.0f);

            int ri  = (int)r;               // trunc toward zero, r >= 0
            int cxi = (int)((x1 + x2) * 0.5f);
            int cyi = (int)((y1 + y2) * 0.5f);

            float sigma = (float)(2 * ri + 1) / 6.0f;
            float neg_inv_2s2 = -1.0f / (2.0f * sigma * sigma);

            // does the (2r+1)^2 patch intersect this tile?
            bool hit = (cxi + ri >= tx) && (cxi - ri <= tx + TILE_W - 1) &&
                       (cyi + ri >= ty) && (cyi - ri <= ty + TILE_H - 1);
            if (hit) {
                s_par[tid] = make_float4((float)cxi, (float)cyi, (float)ri,
                                         neg_inv_2s2);
                int slot = atomicAdd(&s_cnt, 1);
                s_list[slot] = tid;
            }
        }
    }
    __syncthreads();

    // ---- Phase 2: one pixel per thread, max over culled objects ----
    const int px = tx + (tid % TILE_W);     // lane-contiguous -> coalesced
    const int py = ty + (tid / TILE_W);
    const float pxf = (float)px;
    const float pyf = (float)py;

    const int cnt = s_cnt;
    float m = 0.0f;

    #pragma unroll 2
    for (int j = 0; j < cnt; j++) {
        float4 q = s_par[s_list[j]];        // broadcast LDS.128
        float dx = pxf - q.x;
        float dy = pyf - q.y;
        // integers <= 127 are exact in fp32: float compare == int compare
        bool inside = (fabsf(dx) <= q.z) && (fabsf(dy) <= q.z);
        float d2 = dx * dx + dy * dy;
        float g = __expf(d2 * q.w);
        m = fmaxf(m, inside ? g : 0.0f);
    }

    out[batch * (HH * HW) + py * HW + px] = m;
}

extern "C" void kernel_launch(void* const* d_in, const int* in_sizes, int n_in,
                              void* d_out, int out_size) {
    const float* bboxes = (const float*)d_in[1];
    float* out = (float*)d_out;

    dim3 grid(NTILES, HN);   // (64, 16)
    cn_gather_kernel<<<grid, 256>>>(bboxes, out);
}